// round 17
// baseline (speedup 1.0000x reference)
#include <cuda_runtime.h>

#define B 512
#define N 512
#define NB 512
#define THREADS 256
#define R 2                  // rows per CTA
#define GRID (B / R)         // 256 CTAs
#define FULL 0xffffffffu

// Cross-block accumulators (zero at load; last block resets for graph replay).
__device__ double             g_sum   = 0.0;
__device__ unsigned long long g_pairs = 0ULL;
__device__ unsigned int       g_done  = 0u;

// Monotone non-decreasing float -> bucket. Clamped ends are safe: the query
// exact-scans the threshold's own bucket.
__device__ __forceinline__ int bucket_of(float q) {
    float f = (q + 8.0f) * 32.0f;
    f = fminf(fmaxf(f, 0.0f), 511.0f);
    return (int)f;
}

__global__ void __launch_bounds__(THREADS)
fused_kernel(const float* __restrict__ scores,
             const unsigned int* __restrict__ labels,
             float* __restrict__ out) {
    __shared__ int   s_cnt [R][NB];      // histogram counts
    __shared__ float s_sum [R][NB];      // histogram sums
    __shared__ int   s_scnt[R][NB + 2];  // S[b] = count(bucket >= b); S[512]=0
    __shared__ float s_ssum[R][NB + 2];  // Sm[b] = sum(bucket >= b)
    __shared__ int   s_cur [R][NB];      // scatter cursors
    __shared__ float s_scat[R][N];       // negs in descending-bucket order
    __shared__ int   s_gtc [R][8];       // 64-bucket group count totals
    __shared__ float s_gts [R][8];       // 64-bucket group sum totals
    __shared__ float s_redf[8];
    __shared__ int   s_redi[8][R];

    const int tid  = threadIdx.x;
    const int lane = tid & 31;
    const int wrp  = tid >> 5;
    const int row0 = blockIdx.x * R;

    // ---- zero histograms + group totals; issue probe + all score + all
    // speculative int32-view label loads before the bar (all in-bounds under
    // both dtypes; int64 buffer is 2x larger). MLP ~9 overlaps detection.
    #pragma unroll
    for (int r = 0; r < R; r++) {
        s_cnt[r][tid] = 0;  s_cnt[r][tid + 256] = 0;
        s_sum[r][tid] = 0.f; s_sum[r][tid + 256] = 0.f;
    }
    if (tid < R * 8) { s_gtc[tid >> 3][tid & 7] = 0; s_gts[tid >> 3][tid & 7] = 0.f; }

    const unsigned int probe = labels[2 * tid + 1];
    float q[2 * R]; unsigned int u[2 * R];
    #pragma unroll
    for (int r = 0; r < R; r++) {
        const size_t base = (size_t)(row0 + r) * N + tid;
        q[2 * r]     = scores[base];
        q[2 * r + 1] = scores[base + 256];
        u[2 * r]     = labels[base];          // valid iff labels are int32
        u[2 * r + 1] = labels[base + 256];
    }

    const int any_odd = __syncthreads_or(probe != 0u);        // bar 1
    if (!any_odd) {                            // int64: low words
        #pragma unroll
        for (int r = 0; r < R; r++) {
            const size_t base = (size_t)(row0 + r) * N + tid;
            u[2 * r]     = labels[2 * base];
            u[2 * r + 1] = labels[2 * (base + 256)];
        }
    }

    bool neg[2 * R]; int bk[2 * R];
    #pragma unroll
    for (int e = 0; e < 2 * R; e++) { neg[e] = (u[e] == 0u); bk[e] = bucket_of(q[e]); }

    // ---- histogram of negatives (+ group totals: kills the publish barrier)
    #pragma unroll
    for (int e = 0; e < 2 * R; e++) {
        if (neg[e]) {
            const int r = e >> 1;
            atomicAdd(&s_cnt[r][bk[e]], 1);
            atomicAdd(&s_sum[r][bk[e]], q[e]);
            atomicAdd(&s_gtc[r][bk[e] >> 6], 1);
            atomicAdd(&s_gts[r][bk[e] >> 6], q[e]);
        }
    }
    __syncthreads();                                          // bar 2

    // ---- suffix scans (both rows interleaved); lane owns buckets {2t, 2t+1}
    #pragma unroll
    for (int r = 0; r < R; r++) {
        const int2   ci = ((const int2*)s_cnt[r])[tid];
        const float2 mi = ((const float2*)s_sum[r])[tid];
        const int   c0 = ci.x,  c1 = ci.y;
        const float m0 = mi.x,  m1 = mi.y;
        const int   tot  = c0 + c1;
        const float totm = m0 + m1;

        int   sc = tot;   float sm = totm;   // inclusive suffix over lanes
        #pragma unroll
        for (int o = 1; o < 32; o <<= 1) {
            int   a = __shfl_down_sync(FULL, sc, o);
            float b = __shfl_down_sync(FULL, sm, o);
            if (lane + o < 32) { sc += a; sm += b; }
        }
        int   Wc = 0; float Wm = 0.f;        // totals of higher bucket groups
        #pragma unroll
        for (int g = 0; g < 8; g++) {
            if (g > wrp) { Wc += s_gtc[r][g]; Wm += s_gts[r][g]; }
        }
        const int   T  = (sc - tot)  + Wc;   // suffix strictly above bucket 2t+1
        const float Tm = (sm - totm) + Wm;

        ((int2*)s_scnt[r])[tid]   = make_int2(tot + T, c1 + T);
        ((float2*)s_ssum[r])[tid] = make_float2(totm + Tm, m1 + Tm);
        ((int2*)s_cur[r])[tid]    = make_int2(c1 + T, T);
    }
    if (tid < R) { s_scnt[tid][NB] = 0; s_ssum[tid][NB] = 0.f; }
    __syncthreads();                                          // bar 3

    // ---- counting-sort scatter (descending bucket order), both rows
    #pragma unroll
    for (int e = 0; e < 2 * R; e++) {
        if (neg[e]) {
            const int r = e >> 1;
            s_scat[r][atomicAdd(&s_cur[r][bk[e]], 1)] = q[e];
        }
    }
    __syncthreads();                                          // bar 4

    // ---- queries straight from registers (positives only), both rows
    float acc = 0.0f;
    #pragma unroll
    for (int e = 0; e < 2 * R; e++) {
        if (!neg[e]) {
            const int   r = e >> 1;
            const float p = q[e];
            const float t = p - 1.0f;
            const int   b = bucket_of(t);
            const int  st = s_scnt[r][b + 1];   // count(bucket > b): all > t
            const int  en = s_scnt[r][b];
            float cg = (float)st;
            float sg = s_ssum[r][b + 1];
            for (int j = st; j < en; j++) {     // exact scan of bucket b
                const float x = s_scat[r][j];
                if (x > t) { cg += 1.0f; sg += x; }
            }
            acc += cg * (1.0f - p) + sg;
        }
    }

    // ---- reduce: loss via shfl; per-row npos via ballot+popc
    #pragma unroll
    for (int o = 16; o > 0; o >>= 1)
        acc += __shfl_down_sync(FULL, acc, o);
    #pragma unroll
    for (int r = 0; r < R; r++) {
        const int nr = __popc(__ballot_sync(FULL, !neg[2 * r])) +
                       __popc(__ballot_sync(FULL, !neg[2 * r + 1]));
        if (lane == 0) s_redi[wrp][r] = nr;
    }
    if (lane == 0) s_redf[wrp] = acc;
    __syncthreads();                                          // bar 5

    // ---- single-level cross-block accumulate + last-block finalize
    if (tid == 0) {
        float vsum = 0.0f;
        int   np[R];
        #pragma unroll
        for (int r = 0; r < R; r++) np[r] = 0;
        #pragma unroll
        for (int w = 0; w < 8; w++) {
            vsum += s_redf[w];
            #pragma unroll
            for (int r = 0; r < R; r++) np[r] += s_redi[w][r];
        }
        unsigned long long pairs = 0ULL;
        #pragma unroll
        for (int r = 0; r < R; r++)
            pairs += (unsigned long long)np[r] * (unsigned long long)(N - np[r]);

        atomicAdd(&g_sum, (double)vsum);
        atomicAdd(&g_pairs, pairs);
        __threadfence();
        unsigned int ticket = atomicAdd(&g_done, 1u);
        if (ticket == GRID - 1) {
            __threadfence();
            double    s   = atomicAdd(&g_sum, 0.0);
            long long npr = (long long)atomicAdd(&g_pairs, 0ULL);
            out[0] = (npr > 0) ? (float)(s / (double)npr) : 0.0f;
            g_sum   = 0.0;
            g_pairs = 0ULL;
            __threadfence();
            g_done  = 0u;
        }
    }
}

extern "C" void kernel_launch(void* const* d_in, const int* in_sizes, int n_in,
                              void* d_out, int out_size) {
    const float*        scores = (const float*)d_in[0];
    const unsigned int* labels = (const unsigned int*)d_in[1];
    float*              out    = (float*)d_out;

    fused_kernel<<<GRID, THREADS>>>(scores, labels, out);
}